// round 2
// baseline (speedup 1.0000x reference)
#include <cuda_runtime.h>
#include <cuda_bf16.h>
#include <cstdint>

#define T_SEQ   80
#define NCLS    80
#define HID     256
#define EMB     8
#define BATCH   8192
#define GATES   1024
#define M_CTA   64
#define NCTA    (BATCH / M_CTA)
#define NTHREADS 256

#define KT1     17                  // layer1 K = 272 (1 bias + 7 pad + 8 x + 256 h1)
#define KT2     33                  // layer2 K = 528 (adds 256 h2)
#define A_STRIDE   536              // bf16 elems/row; 1072B % 128 = 48 -> conflict-free ldmatrix
#define A_STRIDE_B (A_STRIDE * 2)
#define C_STRIDE   264

#define SM_A        0
#define SM_A_BYTES  (M_CTA * A_STRIDE_B)
#define SM_C1       SM_A_BYTES
#define SM_CBYTES   (M_CTA * C_STRIDE * 4)
#define SM_C2       (SM_C1 + SM_CBYTES)
#define SM_EMB      (SM_C2 + SM_CBYTES)
#define SM_LOGITS   (SM_EMB + NCLS * EMB * 4)
#define SM_TOTAL    (SM_LOGITS + M_CTA * NCLS * 4)   // 226816 bytes

// packed weights: [ntile(128)][ktile(KT)][lane(32)] -> uint2 {b0,b1} m16n8k16 B frag
__device__ uint2 g_W1p[128 * KT1 * 32];
__device__ uint2 g_W2p[128 * KT2 * 32];

// row r of extended weight: r==0 -> bias[n]; 0<r<woff -> 0; else W[r-woff][n]
__global__ void pack_kernel(const float* __restrict__ W, const float* __restrict__ b,
                            int KT, int woff, int which)
{
    int idx = blockIdx.x * blockDim.x + threadIdx.x;
    int total = 128 * KT * 32;
    if (idx >= total) return;
    uint2* out = which ? g_W2p : g_W1p;
    int lane = idx & 31;
    int kt   = (idx >> 5) % KT;
    int nt   = idx / (32 * KT);
    int th = lane & 3, g = lane >> 2;
    int n  = nt * 8 + g;
    int k0 = kt * 16 + th * 2;
    float v[4];
#pragma unroll
    for (int i = 0; i < 4; i++) {
        int r = k0 + ((i >> 1) * 8) + (i & 1);   // k0, k0+1, k0+8, k0+9
        float val;
        if (r == 0)          val = b[n];
        else if (r < woff)   val = 0.f;
        else                 val = W[(size_t)(r - woff) * GATES + n];
        v[i] = val;
    }
    __nv_bfloat162 p0 = __floats2bfloat162_rn(v[0], v[1]);
    __nv_bfloat162 p1 = __floats2bfloat162_rn(v[2], v[3]);
    uint2 o;
    o.x = *reinterpret_cast<uint32_t*>(&p0);
    o.y = *reinterpret_cast<uint32_t*>(&p1);
    out[idx] = o;
}

__device__ __forceinline__ float fast_tanh(float x) {
    float y; asm("tanh.approx.f32 %0, %1;" : "=f"(y) : "f"(x)); return y;
}
__device__ __forceinline__ float fast_sigmoid(float x) {
    return fmaf(fast_tanh(0.5f * x), 0.5f, 0.5f);
}
__device__ __forceinline__ void ldsm4(uint32_t a[4], uint32_t addr) {
    asm volatile("ldmatrix.sync.aligned.m8n8.x4.shared.b16 {%0,%1,%2,%3}, [%4];\n"
                 : "=r"(a[0]), "=r"(a[1]), "=r"(a[2]), "=r"(a[3]) : "r"(addr));
}
__device__ __forceinline__ void mma_bf16(float c[4], const uint32_t a[4], uint32_t b0, uint32_t b1) {
    asm volatile("mma.sync.aligned.m16n8k16.row.col.f32.bf16.bf16.f32 "
                 "{%0,%1,%2,%3}, {%4,%5,%6,%7}, {%8,%9}, {%0,%1,%2,%3};\n"
                 : "+f"(c[0]), "+f"(c[1]), "+f"(c[2]), "+f"(c[3])
                 : "r"(a[0]), "r"(a[1]), "r"(a[2]), "r"(a[3]), "r"(b0), "r"(b1));
}

// One LSTM layer for 64 rows. Warp w, cblk: hidden cols [cblk*64 + w*8, +8), all 4 gates.
template<int KT>
__device__ __forceinline__ void lstm_layer(
    char* smem, uint32_t sbase, const uint2* __restrict__ Wp,
    float* __restrict__ cbuf, uint32_t (&hnew)[4][4][2],
    int w, int lane)
{
    const int th = lane & 3, g = lane >> 2;
    const uint32_t a_addr0 = sbase + (uint32_t)((lane & 15) * A_STRIDE_B + ((lane >> 4) << 4));
#pragma unroll
    for (int cblk = 0; cblk < 4; cblk++) {
        float acc[4][4][4];
#pragma unroll
        for (int mt = 0; mt < 4; mt++)
#pragma unroll
            for (int gi = 0; gi < 4; gi++)
#pragma unroll
                for (int i = 0; i < 4; i++) acc[mt][gi][i] = 0.f;

        const uint2* bp[4];
#pragma unroll
        for (int gi = 0; gi < 4; gi++)
            bp[gi] = Wp + ((size_t)(cblk * 8 + w + gi * 32) * KT) * 32 + lane;

        uint2 bcur[4];
#pragma unroll
        for (int gi = 0; gi < 4; gi++) bcur[gi] = __ldg(&bp[gi][0]);

#pragma unroll 1
        for (int kt = 0; kt < KT; kt++) {
            uint2 bnext[4] = {};
            if (kt + 1 < KT) {
#pragma unroll
                for (int gi = 0; gi < 4; gi++) bnext[gi] = __ldg(&bp[gi][(kt + 1) * 32]);
            }
            uint32_t afrag[4][4];
#pragma unroll
            for (int mt = 0; mt < 4; mt++)
                ldsm4(afrag[mt], a_addr0 + (uint32_t)(mt * (16 * A_STRIDE_B) + kt * 32));
#pragma unroll
            for (int mt = 0; mt < 4; mt++)
#pragma unroll
                for (int gi = 0; gi < 4; gi++)
                    mma_bf16(acc[mt][gi], afrag[mt], bcur[gi].x, bcur[gi].y);
#pragma unroll
            for (int gi = 0; gi < 4; gi++) bcur[gi] = bnext[gi];
        }

        const int hcol = cblk * 64 + w * 8 + th * 2;
#pragma unroll
        for (int mt = 0; mt < 4; mt++) {
#pragma unroll
            for (int half = 0; half < 2; half++) {
                const int r = mt * 16 + g + half * 8;
                float hv[2];
#pragma unroll
                for (int p = 0; p < 2; p++) {
                    const int ci = half * 2 + p;
                    float gi_ = acc[mt][0][ci];
                    float gj_ = acc[mt][1][ci];
                    float gf_ = acc[mt][2][ci];
                    float go_ = acc[mt][3][ci];
                    float* cp = cbuf + r * C_STRIDE + hcol + p;
                    float nc = (*cp) * fast_sigmoid(gf_ + 1.0f)
                             + fast_sigmoid(gi_) * fast_tanh(gj_);
                    *cp = nc;
                    hv[p] = fast_tanh(nc) * fast_sigmoid(go_);
                }
                __nv_bfloat162 hp = __floats2bfloat162_rn(hv[0], hv[1]);
                hnew[cblk][mt][half] = *reinterpret_cast<uint32_t*>(&hp);
            }
        }
    }
}

__device__ __forceinline__ void store_h(char* smem, const uint32_t (&hnew)[4][4][2],
                                        int hoff, int w, int lane)
{
    const int th = lane & 3, g = lane >> 2;
#pragma unroll
    for (int cblk = 0; cblk < 4; cblk++) {
        const int col = hoff + cblk * 64 + w * 8 + th * 2;
#pragma unroll
        for (int mt = 0; mt < 4; mt++)
#pragma unroll
            for (int half = 0; half < 2; half++) {
                const int r = mt * 16 + g + half * 8;
                *reinterpret_cast<uint32_t*>(smem + r * A_STRIDE_B + col * 2) = hnew[cblk][mt][half];
            }
    }
}

__global__ void __launch_bounds__(NTHREADS, 1) lstm_kernel(
    const int* __restrict__ features, const int* __restrict__ labels,
    const float* __restrict__ embedding,
    const float* __restrict__ Wd, const float* __restrict__ bd,
    float* __restrict__ out)
{
    extern __shared__ char smem[];
    const int tid = threadIdx.x;
    const int w = tid >> 5, lane = tid & 31;
    const int rowbase = blockIdx.x * M_CTA;

    float* c1   = (float*)(smem + SM_C1);
    float* c2   = (float*)(smem + SM_C2);
    float* embs = (float*)(smem + SM_EMB);

    for (int i = tid; i < SM_TOTAL / 4; i += NTHREADS)
        ((uint32_t*)smem)[i] = 0u;
    __syncthreads();
    if (tid < M_CTA)   // constant bias-one column of A
        *reinterpret_cast<__nv_bfloat16*>(smem + tid * A_STRIDE_B) = __float2bfloat16(1.0f);
    for (int i = tid; i < NCLS * EMB; i += NTHREADS) embs[i] = embedding[i];
    __syncthreads();

    const uint32_t sbase = (uint32_t)__cvta_generic_to_shared(smem);
    uint32_t hnew[4][4][2];

    for (int t = 0; t < T_SEQ; t++) {
        if (tid < M_CTA) {          // x_t -> A cols 8..15
            int f = features[(rowbase + tid) * T_SEQ + t];
            const float* e = embs + f * EMB;
            uint32_t* dst = reinterpret_cast<uint32_t*>(smem + tid * A_STRIDE_B + 16);
#pragma unroll
            for (int i = 0; i < 4; i++) {
                __nv_bfloat162 p = __floats2bfloat162_rn(e[2 * i], e[2 * i + 1]);
                dst[i] = *reinterpret_cast<uint32_t*>(&p);
            }
        }
        __syncthreads();
        lstm_layer<KT1>(smem, sbase, g_W1p, c1, hnew, w, lane);
        __syncthreads();
        store_h(smem, hnew, 16, w, lane);     // h1 -> cols 16..271
        __syncthreads();
        lstm_layer<KT2>(smem, sbase, g_W2p, c2, hnew, w, lane);
        __syncthreads();
        store_h(smem, hnew, 272, w, lane);    // h2 -> cols 272..527
        __syncthreads();
    }

    // dense + log-softmax loss
    float* logits = (float*)(smem + SM_LOGITS);
    for (int item = tid; item < M_CTA * NCLS; item += NTHREADS) {
        int row = item / NCLS, cls = item - row * NCLS;
        const __nv_bfloat16* h2p = (const __nv_bfloat16*)(smem + row * A_STRIDE_B + 272 * 2);
        float acc = __ldg(&bd[cls]);
#pragma unroll 8
        for (int k = 0; k < HID; k++)
            acc += __bfloat162float(h2p[k]) * __ldg(&Wd[k * NCLS + cls]);
        logits[item] = acc;
    }
    __syncthreads();
    if (tid < M_CTA) {
        const float* lr = logits + tid * NCLS;
        float mx = -1e30f;
        for (int c = 0; c < NCLS; c++) mx = fmaxf(mx, lr[c]);
        float s = 0.f;
        for (int c = 0; c < NCLS; c++) s += __expf(lr[c] - mx);
        int lab = labels[rowbase + tid];
        out[rowbase + tid] = mx + __logf(s) - lr[lab];
    }
}

extern "C" void kernel_launch(void* const* d_in, const int* in_sizes, int n_in,
                              void* d_out, int out_size)
{
    const int*   features  = (const int*)  d_in[0];
    const int*   labels    = (const int*)  d_in[1];
    const float* embedding = (const float*)d_in[2];
    const float* W1        = (const float*)d_in[3];
    const float* b1        = (const float*)d_in[4];
    const float* W2        = (const float*)d_in[5];
    const float* b2        = (const float*)d_in[6];
    const float* Wd        = (const float*)d_in[7];
    const float* bd        = (const float*)d_in[8];
    float* out = (float*)d_out;

    int n1 = 128 * KT1 * 32, n2 = 128 * KT2 * 32;
    pack_kernel<<<(n1 + 255) / 256, 256>>>(W1, b1, KT1, 8, 0);
    pack_kernel<<<(n2 + 255) / 256, 256>>>(W2, b2, KT2, 16, 1);

    cudaFuncSetAttribute(lstm_kernel, cudaFuncAttributeMaxDynamicSharedMemorySize, SM_TOTAL);
    lstm_kernel<<<NCTA, NTHREADS, SM_TOTAL>>>(features, labels, embedding, Wd, bd, out);
}

// round 3
// speedup vs baseline: 1.0216x; 1.0216x over previous
#include <cuda_runtime.h>
#include <cuda_bf16.h>
#include <cstdint>

#define T_SEQ   80
#define NCLS    80
#define HID     256
#define EMB     8
#define BATCH   8192
#define GATES   1024
#define M_CTA   64
#define NCTA    (BATCH / M_CTA)
#define NTHREADS 256

#define KT1     17                  // layer1 K = 272 (1 bias + 7 pad + 8 x + 256 h1)
#define KT2     33                  // layer2 K = 528 (adds 256 h2)
#define A_STRIDE   536              // bf16 elems/row; 1072B % 128 = 48 -> conflict-free ldmatrix
#define A_STRIDE_B (A_STRIDE * 2)
#define C_STRIDE   264

#define SM_A        0
#define SM_A_BYTES  (M_CTA * A_STRIDE_B)
#define SM_C1       SM_A_BYTES
#define SM_CBYTES   (M_CTA * C_STRIDE * 4)
#define SM_C2       (SM_C1 + SM_CBYTES)
#define SM_EMB      (SM_C2 + SM_CBYTES)
#define SM_LOGITS   (SM_EMB + NCLS * EMB * 4)
#define SM_TOTAL    (SM_LOGITS + M_CTA * NCLS * 4)   // 226816 bytes

// Packed weights, gate-interleaved fragment-major:
//   uint2 index = ((nt*KT + kt)*32 + lane)*4 + gi     nt in [0,32), gi in [0,4)
// so one lane's 4 gate fragments for a k-tile are 32 contiguous bytes -> 2x LDG.128.
// Column n = gi*256 + nt*8 + (lane>>2); rows k0..k0+1, k0+8..k0+9 with k0 = kt*16 + (lane&3)*2.
#define N1PK (32 * KT1 * 128)       // uint2 elements for W1
#define N2PK (32 * KT2 * 128)
__device__ uint4 g_W1p[32 * KT1 * 64];   // uint4-typed for 16B alignment
__device__ uint4 g_W2p[32 * KT2 * 64];

// Extended-weight row r: r==0 -> bias[n]; 0<r<woff -> 0; else W[r-woff][n]
__global__ void pack_all(const float* __restrict__ W1, const float* __restrict__ b1,
                         const float* __restrict__ W2, const float* __restrict__ b2)
{
    int idx = blockIdx.x * blockDim.x + threadIdx.x;
    if (idx >= N1PK + N2PK) return;
    const float *W, *b; uint2* out; int KT, woff, rem;
    if (idx < N1PK) { W = W1; b = b1; out = (uint2*)g_W1p; KT = KT1; woff = 8;  rem = idx; }
    else            { W = W2; b = b2; out = (uint2*)g_W2p; KT = KT2; woff = 16; rem = idx - N1PK; }
    int gi   = rem & 3;
    int lane = (rem >> 2) & 31;
    int t    = rem >> 7;
    int kt   = t % KT;
    int nt   = t / KT;
    int th = lane & 3, g = lane >> 2;
    int n  = gi * 256 + nt * 8 + g;
    int k0 = kt * 16 + th * 2;
    float v[4];
#pragma unroll
    for (int i = 0; i < 4; i++) {
        int r = k0 + ((i >> 1) * 8) + (i & 1);   // k0, k0+1, k0+8, k0+9
        float val;
        if (r == 0)          val = b[n];
        else if (r < woff)   val = 0.f;
        else                 val = W[(size_t)(r - woff) * GATES + n];
        v[i] = val;
    }
    __nv_bfloat162 p0 = __floats2bfloat162_rn(v[0], v[1]);
    __nv_bfloat162 p1 = __floats2bfloat162_rn(v[2], v[3]);
    uint2 o;
    o.x = *reinterpret_cast<uint32_t*>(&p0);
    o.y = *reinterpret_cast<uint32_t*>(&p1);
    out[rem] = o;
}

__device__ __forceinline__ float fast_tanh(float x) {
    float y; asm("tanh.approx.f32 %0, %1;" : "=f"(y) : "f"(x)); return y;
}
__device__ __forceinline__ float fast_sigmoid(float x) {
    return fmaf(fast_tanh(0.5f * x), 0.5f, 0.5f);
}
__device__ __forceinline__ void ldsm4(uint32_t a[4], uint32_t addr) {
    asm volatile("ldmatrix.sync.aligned.m8n8.x4.shared.b16 {%0,%1,%2,%3}, [%4];\n"
                 : "=r"(a[0]), "=r"(a[1]), "=r"(a[2]), "=r"(a[3]) : "r"(addr));
}
__device__ __forceinline__ void mma_bf16(float c[4], const uint32_t a[4], uint32_t b0, uint32_t b1) {
    asm volatile("mma.sync.aligned.m16n8k16.row.col.f32.bf16.bf16.f32 "
                 "{%0,%1,%2,%3}, {%4,%5,%6,%7}, {%8,%9}, {%0,%1,%2,%3};\n"
                 : "+f"(c[0]), "+f"(c[1]), "+f"(c[2]), "+f"(c[3])
                 : "r"(a[0]), "r"(a[1]), "r"(a[2]), "r"(a[3]), "r"(b0), "r"(b1));
}

// One LSTM layer for 64 rows. Warp w, cblk: hidden cols [cblk*64 + w*8, +8), all 4 gates.
// B pipeline depth 2 (covers ~2x128 cyc of L2 latency); A ldmatrix pipelined depth 1.
template<int KT>
__device__ __forceinline__ void lstm_layer(
    char* smem, uint32_t sbase, const uint4* __restrict__ Wp,
    float* __restrict__ cbuf, uint32_t (&hnew)[4][4][2],
    int w, int lane)
{
    const int th = lane & 3, g = lane >> 2;
    const uint32_t a_addr0 = sbase + (uint32_t)((lane & 15) * A_STRIDE_B + ((lane >> 4) << 4));
#pragma unroll
    for (int cblk = 0; cblk < 4; cblk++) {
        float acc[4][4][4];
#pragma unroll
        for (int mt = 0; mt < 4; mt++)
#pragma unroll
            for (int gi = 0; gi < 4; gi++)
#pragma unroll
                for (int i = 0; i < 4; i++) acc[mt][gi][i] = 0.f;

        // per-warp, per-lane base into packed weights (uint4 units)
        const uint4* bb = Wp + ((size_t)(cblk * 8 + w) * KT * 32 + lane) * 2;

        uint4 bc0 = __ldg(bb),      bc1 = __ldg(bb + 1);        // kt
        uint4 b10 = __ldg(bb + 64), b11 = __ldg(bb + 65);       // kt+1

        uint32_t af[4][4];
#pragma unroll
        for (int mt = 0; mt < 4; mt++)
            ldsm4(af[mt], a_addr0 + (uint32_t)(mt * (16 * A_STRIDE_B)));

#pragma unroll 1
        for (int kt = 0; kt < KT; kt++) {
            uint4 b20 = {0,0,0,0}, b21 = {0,0,0,0};             // kt+2 prefetch
            if (kt + 2 < KT) {
                b20 = __ldg(bb + (kt + 2) * 64);
                b21 = __ldg(bb + (kt + 2) * 64 + 1);
            }
#pragma unroll
            for (int mt = 0; mt < 4; mt++) {
                mma_bf16(acc[mt][0], af[mt], bc0.x, bc0.y);
                mma_bf16(acc[mt][1], af[mt], bc0.z, bc0.w);
                mma_bf16(acc[mt][2], af[mt], bc1.x, bc1.y);
                mma_bf16(acc[mt][3], af[mt], bc1.z, bc1.w);
            }
            if (kt + 1 < KT) {                                  // A prefetch for kt+1
#pragma unroll
                for (int mt = 0; mt < 4; mt++)
                    ldsm4(af[mt], a_addr0 + (uint32_t)(mt * (16 * A_STRIDE_B) + (kt + 1) * 32));
            }
            bc0 = b10; bc1 = b11; b10 = b20; b11 = b21;
        }

        const int hcol = cblk * 64 + w * 8 + th * 2;
#pragma unroll
        for (int mt = 0; mt < 4; mt++) {
#pragma unroll
            for (int half = 0; half < 2; half++) {
                const int r = mt * 16 + g + half * 8;
                float hv[2];
#pragma unroll
                for (int p = 0; p < 2; p++) {
                    const int ci = half * 2 + p;
                    float gi_ = acc[mt][0][ci];
                    float gj_ = acc[mt][1][ci];
                    float gf_ = acc[mt][2][ci];
                    float go_ = acc[mt][3][ci];
                    float* cp = cbuf + r * C_STRIDE + hcol + p;
                    float nc = (*cp) * fast_sigmoid(gf_ + 1.0f)
                             + fast_sigmoid(gi_) * fast_tanh(gj_);
                    *cp = nc;
                    hv[p] = fast_tanh(nc) * fast_sigmoid(go_);
                }
                __nv_bfloat162 hp = __floats2bfloat162_rn(hv[0], hv[1]);
                hnew[cblk][mt][half] = *reinterpret_cast<uint32_t*>(&hp);
            }
        }
    }
}

__device__ __forceinline__ void store_h(char* smem, const uint32_t (&hnew)[4][4][2],
                                        int hoff, int w, int lane)
{
    const int th = lane & 3, g = lane >> 2;
#pragma unroll
    for (int cblk = 0; cblk < 4; cblk++) {
        const int col = hoff + cblk * 64 + w * 8 + th * 2;
#pragma unroll
        for (int mt = 0; mt < 4; mt++)
#pragma unroll
            for (int half = 0; half < 2; half++) {
                const int r = mt * 16 + g + half * 8;
                *reinterpret_cast<uint32_t*>(smem + r * A_STRIDE_B + col * 2) = hnew[cblk][mt][half];
            }
    }
}

__global__ void __launch_bounds__(NTHREADS, 1) lstm_kernel(
    const int* __restrict__ features, const int* __restrict__ labels,
    const float* __restrict__ embedding,
    const float* __restrict__ Wd, const float* __restrict__ bd,
    float* __restrict__ out)
{
    extern __shared__ char smem[];
    const int tid = threadIdx.x;
    const int w = tid >> 5, lane = tid & 31;
    const int rowbase = blockIdx.x * M_CTA;

    float* c1   = (float*)(smem + SM_C1);
    float* c2   = (float*)(smem + SM_C2);
    float* embs = (float*)(smem + SM_EMB);

    for (int i = tid; i < SM_TOTAL / 4; i += NTHREADS)
        ((uint32_t*)smem)[i] = 0u;
    __syncthreads();
    if (tid < M_CTA)   // constant bias-one column of A
        *reinterpret_cast<__nv_bfloat16*>(smem + tid * A_STRIDE_B) = __float2bfloat16(1.0f);
    for (int i = tid; i < NCLS * EMB; i += NTHREADS) embs[i] = embedding[i];
    __syncthreads();

    const uint32_t sbase = (uint32_t)__cvta_generic_to_shared(smem);
    uint32_t hnew[4][4][2];

    for (int t = 0; t < T_SEQ; t++) {
        if (tid < M_CTA) {          // x_t -> A cols 8..15
            int f = features[(rowbase + tid) * T_SEQ + t];
            const float* e = embs + f * EMB;
            uint32_t* dst = reinterpret_cast<uint32_t*>(smem + tid * A_STRIDE_B + 16);
#pragma unroll
            for (int i = 0; i < 4; i++) {
                __nv_bfloat162 p = __floats2bfloat162_rn(e[2 * i], e[2 * i + 1]);
                dst[i] = *reinterpret_cast<uint32_t*>(&p);
            }
        }
        __syncthreads();
        lstm_layer<KT1>(smem, sbase, g_W1p, c1, hnew, w, lane);
        __syncthreads();
        store_h(smem, hnew, 16, w, lane);     // h1 -> cols 16..271
        __syncthreads();
        lstm_layer<KT2>(smem, sbase, g_W2p, c2, hnew, w, lane);
        __syncthreads();
        store_h(smem, hnew, 272, w, lane);    // h2 -> cols 272..527
        __syncthreads();
    }

    // dense + log-softmax loss
    float* logits = (float*)(smem + SM_LOGITS);
    for (int item = tid; item < M_CTA * NCLS; item += NTHREADS) {
        int row = item / NCLS, cls = item - row * NCLS;
        const __nv_bfloat16* h2p = (const __nv_bfloat16*)(smem + row * A_STRIDE_B + 272 * 2);
        float acc = __ldg(&bd[cls]);
#pragma unroll 8
        for (int k = 0; k < HID; k++)
            acc += __bfloat162float(h2p[k]) * __ldg(&Wd[k * NCLS + cls]);
        logits[item] = acc;
    }
    __syncthreads();
    if (tid < M_CTA) {
        const float* lr = logits + tid * NCLS;
        float mx = -1e30f;
        for (int c = 0; c < NCLS; c++) mx = fmaxf(mx, lr[c]);
        float s = 0.f;
        for (int c = 0; c < NCLS; c++) s += __expf(lr[c] - mx);
        int lab = labels[rowbase + tid];
        out[rowbase + tid] = mx + __logf(s) - lr[lab];
    }
}

extern "C" void kernel_launch(void* const* d_in, const int* in_sizes, int n_in,
                              void* d_out, int out_size)
{
    const int*   features  = (const int*)  d_in[0];
    const int*   labels    = (const int*)  d_in[1];
    const float* embedding = (const float*)d_in[2];
    const float* W1        = (const float*)d_in[3];
    const float* b1        = (const float*)d_in[4];
    const float* W2        = (const float*)d_in[5];
    const float* b2        = (const float*)d_in[6];
    const float* Wd        = (const float*)d_in[7];
    const float* bd        = (const float*)d_in[8];
    float* out = (float*)d_out;

    int ntot = N1PK + N2PK;
    pack_all<<<(ntot + 255) / 256, 256>>>(W1, b1, W2, b2);

    cudaFuncSetAttribute(lstm_kernel, cudaFuncAttributeMaxDynamicSharedMemorySize, SM_TOTAL);
    lstm_kernel<<<NCTA, NTHREADS, SM_TOTAL>>>(features, labels, embedding, Wd, bd, out);
}